// round 5
// baseline (speedup 1.0000x reference)
#include <cuda_runtime.h>

#define BATCH   128
#define NANCH   8732
#define NCLS    21
#define NLOG    25
#define MAXOUT  5
#define CONF    0.5f
#define APB     256                        // anchors per block
#define NSLICE  ((NANCH + APB - 1) / APB)  // 35 (34 full + tail of 28)

// Device globals (zero-init at load; restored to zero every launch by the
// last block of each batch -> graph-replay consistent, no reset kernel).
__device__ int                 g_cnt[BATCH];
__device__ int                 g_done[BATCH];
__device__ float4              g_cbox[BATCH * NANCH];
__device__ unsigned long long  g_ckey[BATCH * NANCH];
__device__ float               g_ccls[BATCH * NANCH];

// ---------------------------------------------------------------------------
// Fused kernel: decode + softmax-max/argmax + candidate compaction; the
// last-arriving block of each batch then performs that batch's NMS inline.
// grid = (NSLICE, BATCH), block = APB threads, one anchor per thread.
// ---------------------------------------------------------------------------
__global__ void __launch_bounds__(APB)
fused_kernel(const float* __restrict__ logits, const float* __restrict__ db,
             float* __restrict__ out) {
    __shared__ float tile[APB * NLOG];
    __shared__ int   s_last;

    int b     = blockIdx.y;
    int slice = blockIdx.x;
    int tid   = threadIdx.x;

    int a0      = slice * APB;                       // first anchor of slice
    int nvalid  = min(APB, NANCH - a0);              // anchors in this slice
    int nv      = nvalid * NLOG / 4;                 // float4s to stage (25*nvalid divisible by 4? 25*256=6400/4 ok; 25*28=700/4 ok)

    const float4* __restrict__ src =
        (const float4*)(logits + ((size_t)b * NANCH + a0) * NLOG);
    float4* dst = (float4*)tile;

    // front-batched staging: up to 7 independent LDG.128 per thread
    float4 v[7];
#pragma unroll
    for (int k = 0; k < 7; k++) {
        int i = tid + k * APB;
        if (i < nv) v[k] = src[i];
    }
#pragma unroll
    for (int k = 0; k < 7; k++) {
        int i = tid + k * APB;
        if (i < nv) dst[i] = v[k];
    }
    __syncthreads();

    int n = a0 + tid;                                // global anchor index
    if (tid < nvalid) {
        const float* L = tile + tid * NLOG;

        float best = L[4];
        int   bi   = 0;
#pragma unroll
        for (int c = 1; c < NCLS; c++) {
            float vv = L[4 + c];
            if (vv > best) { best = vv; bi = c; }
        }
        float sum = 0.f;
#pragma unroll
        for (int c = 0; c < NCLS; c++) sum += __expf(L[4 + c] - best);
        float score = 1.0f / sum;

        if (bi != 0 && score > CONF) {
            float4 d = ((const float4*)db)[n];       // y0,x0,y1,x1
            float cy = 0.5f * (d.z + d.x);
            float cx = 0.5f * (d.w + d.y);
            float h  = d.z - d.x;
            float w  = d.w - d.y;
            float ncy = L[0] * h + cy;
            float ncx = L[1] * w + cx;
            float nh  = __expf(L[2]) * h;
            float nw  = __expf(L[3]) * w;
            float4 box;
            box.x = fminf(fmaxf(ncy - 0.5f * nh, 0.f), 1.f);
            box.y = fminf(fmaxf(ncx - 0.5f * nw, 0.f), 1.f);
            box.z = fminf(fmaxf(ncy + 0.5f * nh, 0.f), 1.f);
            box.w = fminf(fmaxf(ncx + 0.5f * nw, 0.f), 1.f);

            int slot = atomicAdd(&g_cnt[b], 1);
            size_t o = (size_t)b * NANCH + slot;
            // key: [score bits|0x80000000][NANCH-n : 14b][slot : 14b]
            unsigned hi = __float_as_uint(score) | 0x80000000u;
            unsigned lo = ((unsigned)(NANCH - n) << 14) | (unsigned)slot;
            g_ckey[o] = ((unsigned long long)hi << 32) | lo;
            g_cbox[o] = box;
            g_ccls[o] = (float)bi;
        }
    }

    // ---- release: make this block's candidate writes device-visible ----
    __threadfence();
    __syncthreads();
    if (tid == 0) {
        int prior = atomicAdd(&g_done[b], 1);
        s_last = (prior == NSLICE - 1);
    }
    __syncthreads();
    if (!s_last) return;

    // =======================================================================
    // Last block of batch b: run NMS inline (warp 0 only, fused
    // suppress+argmax, candidate list read from L2 — M is small).
    // =======================================================================
    if (tid >= 32) return;
    __threadfence();                                  // acquire side

    int M = g_cnt[b];
    size_t base = (size_t)b * NANCH;
    unsigned long long* keys  = g_ckey + base;
    const float4*       boxes = g_cbox + base;
    const float*        cls   = g_ccls + base;

    unsigned long long bp = 0ull;
    for (int i = tid; i < M; i += 32) {
        unsigned long long k = keys[i];
        if (k > bp) bp = k;
    }
#pragma unroll
    for (int off = 16; off > 0; off >>= 1) {
        unsigned long long o = __shfl_xor_sync(0xffffffffu, bp, off);
        if (o > bp) bp = o;
    }

    float* ob = out + (size_t)b * MAXOUT * 6;
    for (int t = 0; t < MAXOUT; t++) {
        if (bp == 0ull) {
            if (tid == 0) {
                for (int tt = t; tt < MAXOUT; tt++) {
                    float* o = ob + tt * 6;
                    o[0] = o[1] = o[2] = o[3] = o[4] = o[5] = 0.f;
                }
            }
            break;
        }
        int   pos = (int)(bp & 0x3FFFull);
        float sc  = __uint_as_float((unsigned)(bp >> 32) & 0x7FFFFFFFu);
        float4 B  = boxes[pos];
        if (tid == 0) {
            float* o = ob + t * 6;
            o[0] = B.x; o[1] = B.y; o[2] = B.z; o[3] = B.w;
            o[4] = cls[pos]; o[5] = sc;
        }
        if (t == MAXOUT - 1) break;

        float a1 = (B.z - B.x) * (B.w - B.y);
        bp = 0ull;
        for (int i = tid; i < M; i += 32) {
            unsigned long long k = keys[i];
            if (!k) continue;
            float4 C = boxes[i];
            float ty  = fmaxf(B.x, C.x);
            float tx  = fmaxf(B.y, C.y);
            float by  = fminf(B.z, C.z);
            float bxr = fminf(B.w, C.w);
            float hh  = fmaxf(by - ty, 0.f);
            float ww  = fmaxf(bxr - tx, 0.f);
            float inter = hh * ww;
            float a2 = (C.z - C.x) * (C.w - C.y);
            float iou = inter / (a1 + a2 - inter + 1e-12f);
            if (iou > 0.5f) keys[i] = 0ull;
            else if (k > bp) bp = k;
        }
#pragma unroll
        for (int off = 16; off > 0; off >>= 1) {
            unsigned long long o = __shfl_xor_sync(0xffffffffu, bp, off);
            if (o > bp) bp = o;
        }
    }

    // reset counters for the next graph replay
    if (tid == 0) {
        g_cnt[b]  = 0;
        g_done[b] = 0;
    }
}

// ---------------------------------------------------------------------------
extern "C" void kernel_launch(void* const* d_in, const int* in_sizes, int n_in,
                              void* d_out, int out_size) {
    const float* logits = (const float*)d_in[0];   // [128, 8732, 25]
    const float* db     = (const float*)d_in[1];   // [8732, 4]
    float*       out    = (float*)d_out;           // [128, 5, 6]

    dim3 grid(NSLICE, BATCH);
    fused_kernel<<<grid, APB>>>(logits, db, out);
}

// round 6
// speedup vs baseline: 1.0471x; 1.0471x over previous
#include <cuda_runtime.h>

#define BATCH   128
#define NANCH   8732
#define NCLS    21
#define NLOG    25
#define MAXOUT  5
#define CONF    0.5f
#define APB     256                        // anchors per block
#define NSLICE  ((NANCH + APB - 1) / APB)  // 35
#define CSTRIDE 32                         // counter pad: 32 ints = 128 B

// Device globals (zero-init at load; restored to zero every launch by the
// last block of each batch -> graph-replay consistent, no reset kernel).
// Counters padded to 128B stride: independent L2 atomic units per batch.
__device__ int                 g_cnt[BATCH * CSTRIDE];
__device__ int                 g_done[BATCH * CSTRIDE];
__device__ float4              g_cbox[BATCH * NANCH];
__device__ unsigned long long  g_ckey[BATCH * NANCH];
__device__ float               g_ccls[BATCH * NANCH];

// ---------------------------------------------------------------------------
// Fused kernel: decode + softmax-max/argmax + candidate compaction; the
// last-arriving block of each batch performs that batch's NMS inline.
// grid = (NSLICE, BATCH), block = APB threads, one anchor per thread.
// ---------------------------------------------------------------------------
__global__ void __launch_bounds__(APB)
fused_kernel(const float* __restrict__ logits, const float* __restrict__ db,
             float* __restrict__ out) {
    __shared__ float tile[APB * NLOG];
    __shared__ int   s_last;

    int b     = blockIdx.y;
    int slice = blockIdx.x;
    int tid   = threadIdx.x;

    int a0     = slice * APB;
    int nvalid = min(APB, NANCH - a0);
    int nv     = nvalid * NLOG / 4;                  // float4s to stage

    const float4* __restrict__ src =
        (const float4*)(logits + ((size_t)b * NANCH + a0) * NLOG);
    float4* dst = (float4*)tile;

    // front-batched staging: up to 7 independent LDG.128 per thread
    float4 v[7];
#pragma unroll
    for (int k = 0; k < 7; k++) {
        int i = tid + k * APB;
        if (i < nv) v[k] = src[i];
    }
#pragma unroll
    for (int k = 0; k < 7; k++) {
        int i = tid + k * APB;
        if (i < nv) dst[i] = v[k];
    }
    __syncthreads();

    int n = a0 + tid;
    if (tid < nvalid) {
        const float* L = tile + tid * NLOG;

        float best = L[4];
        int   bi   = 0;
#pragma unroll
        for (int c = 1; c < NCLS; c++) {
            float vv = L[4 + c];
            if (vv > best) { best = vv; bi = c; }
        }
        float sum = 0.f;
#pragma unroll
        for (int c = 0; c < NCLS; c++) sum += __expf(L[4 + c] - best);
        float score = 1.0f / sum;

        if (bi != 0 && score > CONF) {
            float4 d = ((const float4*)db)[n];       // y0,x0,y1,x1
            float cy = 0.5f * (d.z + d.x);
            float cx = 0.5f * (d.w + d.y);
            float h  = d.z - d.x;
            float w  = d.w - d.y;
            float ncy = L[0] * h + cy;
            float ncx = L[1] * w + cx;
            float nh  = __expf(L[2]) * h;
            float nw  = __expf(L[3]) * w;
            float4 box;
            box.x = fminf(fmaxf(ncy - 0.5f * nh, 0.f), 1.f);
            box.y = fminf(fmaxf(ncx - 0.5f * nw, 0.f), 1.f);
            box.z = fminf(fmaxf(ncy + 0.5f * nh, 0.f), 1.f);
            box.w = fminf(fmaxf(ncx + 0.5f * nw, 0.f), 1.f);

            int slot = atomicAdd(&g_cnt[b * CSTRIDE], 1);
            size_t o = (size_t)b * NANCH + slot;
            // key: [score bits|0x80000000][NANCH-n : 14b][slot : 14b]
            unsigned hi = __float_as_uint(score) | 0x80000000u;
            unsigned lo = ((unsigned)(NANCH - n) << 14) | (unsigned)slot;
            g_ckey[o] = ((unsigned long long)hi << 32) | lo;
            g_cbox[o] = box;
            g_ccls[o] = (float)bi;
        }
    }

    // ---- publish: block barrier (makes all block writes visible to tid 0),
    // then ONE gpu-scope fence + atomic by tid 0 (cumulative release).
    __syncthreads();
    if (tid == 0) {
        __threadfence();
        int prior = atomicAdd(&g_done[b * CSTRIDE], 1);
        s_last = (prior == NSLICE - 1);
    }
    __syncthreads();
    if (!s_last) return;

    // =======================================================================
    // Last block of batch b: NMS inline (warp 0, fused suppress+argmax).
    // Candidate list read from L2 — M is small.
    // =======================================================================
    if (tid >= 32) return;
    __threadfence();                                  // acquire

    int M = g_cnt[b * CSTRIDE];
    size_t base = (size_t)b * NANCH;
    unsigned long long* keys  = g_ckey + base;
    const float4*       boxes = g_cbox + base;
    const float*        cls   = g_ccls + base;

    unsigned long long bp = 0ull;
    for (int i = tid; i < M; i += 32) {
        unsigned long long k = keys[i];
        if (k > bp) bp = k;
    }
#pragma unroll
    for (int off = 16; off > 0; off >>= 1) {
        unsigned long long o = __shfl_xor_sync(0xffffffffu, bp, off);
        if (o > bp) bp = o;
    }

    float* ob = out + (size_t)b * MAXOUT * 6;
    for (int t = 0; t < MAXOUT; t++) {
        if (bp == 0ull) {
            if (tid == 0) {
                for (int tt = t; tt < MAXOUT; tt++) {
                    float* o = ob + tt * 6;
                    o[0] = o[1] = o[2] = o[3] = o[4] = o[5] = 0.f;
                }
            }
            break;
        }
        int   pos = (int)(bp & 0x3FFFull);
        float sc  = __uint_as_float((unsigned)(bp >> 32) & 0x7FFFFFFFu);
        float4 B  = boxes[pos];
        if (tid == 0) {
            float* o = ob + t * 6;
            o[0] = B.x; o[1] = B.y; o[2] = B.z; o[3] = B.w;
            o[4] = cls[pos]; o[5] = sc;
        }
        if (t == MAXOUT - 1) break;

        float a1 = (B.z - B.x) * (B.w - B.y);
        bp = 0ull;
        for (int i = tid; i < M; i += 32) {
            unsigned long long k = keys[i];
            if (!k) continue;
            float4 C = boxes[i];
            float ty  = fmaxf(B.x, C.x);
            float tx  = fmaxf(B.y, C.y);
            float by  = fminf(B.z, C.z);
            float bxr = fminf(B.w, C.w);
            float hh  = fmaxf(by - ty, 0.f);
            float ww  = fmaxf(bxr - tx, 0.f);
            float inter = hh * ww;
            float a2 = (C.z - C.x) * (C.w - C.y);
            float iou = inter / (a1 + a2 - inter + 1e-12f);
            if (iou > 0.5f) keys[i] = 0ull;
            else if (k > bp) bp = k;
        }
#pragma unroll
        for (int off = 16; off > 0; off >>= 1) {
            unsigned long long o = __shfl_xor_sync(0xffffffffu, bp, off);
            if (o > bp) bp = o;
        }
    }

    // reset counters for next graph replay
    if (tid == 0) {
        g_cnt[b * CSTRIDE]  = 0;
        g_done[b * CSTRIDE] = 0;
    }
}

// ---------------------------------------------------------------------------
extern "C" void kernel_launch(void* const* d_in, const int* in_sizes, int n_in,
                              void* d_out, int out_size) {
    const float* logits = (const float*)d_in[0];   // [128, 8732, 25]
    const float* db     = (const float*)d_in[1];   // [8732, 4]
    float*       out    = (float*)d_out;           // [128, 5, 6]

    dim3 grid(NSLICE, BATCH);
    fused_kernel<<<grid, APB>>>(logits, db, out);
}